// round 3
// baseline (speedup 1.0000x reference)
#include <cuda_runtime.h>

// selfAttn2d, round 3: LDS.128 everywhere, dual-aligned patch copy (no repack
// in conv), transposed w_deconv for 1x LDG.128 per channel in phase 3.

typedef unsigned long long u64;

__device__ __forceinline__ u64 pack2(float lo, float hi) {
    u64 r; asm("mov.b64 %0,{%1,%2};" : "=l"(r) : "f"(lo), "f"(hi)); return r;
}
__device__ __forceinline__ u64 ffma2(u64 a, u64 b, u64 c) {
    u64 d; asm("fma.rn.f32x2 %0,%1,%2,%3;" : "=l"(d) : "l"(a), "l"(b), "l"(c)); return d;
}
__device__ __forceinline__ u64 fmul2(u64 a, u64 b) {
    u64 d; asm("mul.rn.f32x2 %0,%1,%2;" : "=l"(d) : "l"(a), "l"(b)); return d;
}
__device__ __forceinline__ u64 fadd2(u64 a, u64 b) {
    u64 d; asm("add.rn.f32x2 %0,%1,%2;" : "=l"(d) : "l"(a), "l"(b)); return d;
}

// Transposed weights (filled by prep_kernel each launch).
__device__ float g_wqt[64 * 64];      // [c][o]
__device__ float g_wkt[64 * 64];
__device__ float g_wvt[64 * 64];
__device__ float g_wpt[64 * 64];      // w_proj [j][o]
__device__ float g_wrt[576 * 64];     // w_rel  [(c*9+u)][ch]
__device__ float g_wdt[64 * 1024];    // w_deconv [ch][n][eg][bd][e]

__global__ void prep_kernel(const float* __restrict__ wq,
                            const float* __restrict__ wk,
                            const float* __restrict__ wv,
                            const float* __restrict__ w_rel,
                            const float* __restrict__ w_deconv,
                            const float* __restrict__ w_proj)
{
    const int i0 = blockIdx.x * blockDim.x + threadIdx.x;
    const int stride = gridDim.x * blockDim.x;
    for (int i = i0; i < 4096; i += stride) {
        int o = i >> 6, c = i & 63;
        int d = (c << 6) | o;
        g_wqt[d] = wq[i];
        g_wkt[d] = wk[i];
        g_wvt[d] = wv[i];
        g_wpt[d] = w_proj[i];
    }
    for (int j = i0; j < 36864; j += stride) {
        int ch = j / 576, r = j - ch * 576;
        g_wrt[r * 64 + ch] = w_rel[j];
    }
    for (int j = i0; j < 65536; j += stride) {
        int ch = j >> 10;
        int rem = j & 1023;
        int n  = rem >> 8;
        int eg = (rem >> 6) & 3;
        int bd = (rem >> 2) & 15;
        int e  = rem & 3;
        g_wdt[j] = w_deconv[ch * 1024 + (n * 16 + eg * 4 + e) * 16 + bd];
    }
}

__global__ __launch_bounds__(256, 2)
void selfattn2d_kernel(const float* __restrict__ x,
                       const float* __restrict__ w_sf1,
                       const float* __restrict__ b_sf1,
                       const float* __restrict__ w_sf2,
                       const float* __restrict__ b_sf2,
                       const float* __restrict__ b_proj,
                       float* __restrict__ out)
{
    // smemA layout (floats):
    //   [0..3071]    even patch copy: [c][row(6)][8], vals s0..s5 + 2 pad
    //   [3072..4607] odd patch copy:  [c][row(6)][4], vals s1..s4 (16B rows)
    //   [4608..5631] sp_lin [c][16]
    //   phase 3 reuses [0..4095] for packed partials (2048 u64)
    //   phase 4 reuses [0..1023] for attn staging
    __shared__ __align__(16) float smemA[5632];
    __shared__ __align__(16) float q_s[4][16][16];   // [n][e][ac]
    __shared__ __align__(16) float k_s[4][16][16];
    __shared__ __align__(16) float v_s[4][16][16];
    __shared__ __align__(16) float relc_s[64][16];   // [ch][ac]
    __shared__ __align__(16) float rl_s[4][16][16];  // [n][bd][ac]
    __shared__ float csum[64];

    const int pb = blockIdx.x;
    const int b  = pb >> 10;
    const int oy = (pb >> 5) & 31;
    const int ox = pb & 31;
    const int t  = threadIdx.x;

    // ---------------- Phase 0: load patch (dual-aligned copies) ----------------
    {
        const float* xb = x + b * (64 * 64 * 64);
        for (int idx = t; idx < 3072; idx += 256) {
            int c  = idx / 48;
            int r  = idx - c * 48;
            int ii = r >> 3;   // 0..5
            int jj = r & 7;    // 0..7
            int gy = oy * 2 + ii - 2;
            int gx = ox * 2 + jj - 2;
            float val = 0.f;
            bool inrow = (ii >= 1 && ii <= 4);
            bool incol = (jj >= 1 && jj <= 4);
            if (inrow && incol && gy >= 0 && gy < 64 && gx >= 0 && gx < 64)
                val = xb[c * 4096 + gy * 64 + gx];
            smemA[idx] = val;
            if (incol) {
                smemA[3072 + (c * 6 + ii) * 4 + (jj - 1)] = val;   // odd copy
                if (inrow)
                    smemA[4608 + c * 16 + (ii - 1) * 4 + (jj - 1)] = val;
            }
        }
    }
    __syncthreads();

    // ---------------- Phase 1: q / k / v (LDS.128 + f32x2) ----------------
    if (t < 192) {
        const int m = t >> 6;   // 0=q 1=k 2=v
        const int o = t & 63;
        const float* Wt = (m == 0) ? g_wqt : (m == 1) ? g_wkt : g_wvt;
        u64 acc2[8];
#pragma unroll
        for (int p = 0; p < 8; p++) acc2[p] = 0ull;
#pragma unroll 4
        for (int c = 0; c < 64; c++) {
            float w = Wt[(c << 6) | o];
            u64 w2 = pack2(w, w);
            const ulonglong2* row = (const ulonglong2*)(smemA + 4608 + c * 16);
#pragma unroll
            for (int p2 = 0; p2 < 4; p2++) {
                ulonglong2 rv = row[p2];
                acc2[p2 * 2 + 0] = ffma2(w2, rv.x, acc2[p2 * 2 + 0]);
                acc2[p2 * 2 + 1] = ffma2(w2, rv.y, acc2[p2 * 2 + 1]);
            }
        }
        const int n = o >> 4, e = o & 15;
        u64* dst = (m == 0) ? (u64*)&q_s[n][e][0] : (m == 1) ? (u64*)&k_s[n][e][0] : (u64*)&v_s[n][e][0];
        if (m == 0) {
            const u64 s2 = pack2(0.25f, 0.25f);
#pragma unroll
            for (int p = 0; p < 8; p++) dst[p] = fmul2(acc2[p], s2);
        } else {
#pragma unroll
            for (int p = 0; p < 8; p++) dst[p] = acc2[p];
        }
    }

    // ---------------- Phase 2: rel_c (3x3 conv, no repacking) ----------------
    {
        const int ch = t >> 2;
        const int cp = t & 3;
        u64 acc2[8];   // [i][jp]
#pragma unroll
        for (int p = 0; p < 8; p++) acc2[p] = 0ull;
        for (int cc = 0; cc < 16; cc++) {
            const int c = cp * 16 + cc;
            const float* ebase = smemA + c * 48;
            const float* obase = smemA + 3072 + c * 24;
            u64 A[6][3], B[6][2];
#pragma unroll
            for (int r = 0; r < 6; r++) {
                ulonglong2 ev = *(const ulonglong2*)(ebase + r * 8);     // (s0,s1),(s2,s3)
                u64 a2        = *(const u64*)(ebase + r * 8 + 4);        // (s4,s5)
                ulonglong2 ov = *(const ulonglong2*)(obase + r * 4);     // (s1,s2),(s3,s4)
                A[r][0] = ev.x; A[r][1] = ev.y; A[r][2] = a2;
                B[r][0] = ov.x; B[r][1] = ov.y;
            }
            const float* wr = g_wrt + c * 9 * 64 + ch;
            float wf[9];
#pragma unroll
            for (int u = 0; u < 9; u++) wf[u] = wr[u * 64];
#pragma unroll
            for (int di = 0; di < 3; di++) {
#pragma unroll
                for (int dj = 0; dj < 3; dj++) {
                    const u64 w2 = pack2(wf[di * 3 + dj], wf[di * 3 + dj]);
#pragma unroll
                    for (int i = 0; i < 4; i++) {
                        const int r = i + di;
                        u64 X0 = (dj == 0) ? A[r][0] : (dj == 1) ? B[r][0] : A[r][1];
                        u64 X1 = (dj == 0) ? A[r][1] : (dj == 1) ? B[r][1] : A[r][2];
                        acc2[i * 2 + 0] = ffma2(w2, X0, acc2[i * 2 + 0]);
                        acc2[i * 2 + 1] = ffma2(w2, X1, acc2[i * 2 + 1]);
                    }
                }
            }
        }
        // reduce the 4 c-quarters (consecutive lanes), packed adds
#pragma unroll
        for (int p = 0; p < 8; p++) {
            u64 v = acc2[p];
            v = fadd2(v, __shfl_down_sync(0xffffffffu, v, 1));
            v = fadd2(v, __shfl_down_sync(0xffffffffu, v, 2));
            if (cp == 0) ((u64*)&relc_s[ch][0])[p] = v;
        }
    }
    __syncthreads();

    // ---------------- Phase 3: fused rel + q contraction ----------------
    {
        const int bd = t & 15;
        const int n  = (t >> 4) & 3;
        const int eg = t >> 6;            // 4 e's per thread
        // preload q pairs: loop-invariant over ch
        u64 q2[32];
#pragma unroll
        for (int e = 0; e < 4; e++) {
            const ulonglong2* qr = (const ulonglong2*)&q_s[n][eg * 4 + e][0];
#pragma unroll
            for (int p2 = 0; p2 < 4; p2++) {
                ulonglong2 qv = qr[p2];
                q2[e * 8 + p2 * 2 + 0] = qv.x;
                q2[e * 8 + p2 * 2 + 1] = qv.y;
            }
        }
        u64 acc2[8];
#pragma unroll
        for (int p = 0; p < 8; p++) acc2[p] = 0ull;
        const float4* wd4 = (const float4*)(g_wdt + n * 256 + eg * 64 + bd * 4);
#pragma unroll 2
        for (int ch = 0; ch < 64; ch++) {
            float4 wv4 = wd4[ch * 256];   // 1 coalesced LDG.128: e quad
            u64 W0 = pack2(wv4.x, wv4.x), W1 = pack2(wv4.y, wv4.y);
            u64 W2 = pack2(wv4.z, wv4.z), W3 = pack2(wv4.w, wv4.w);
            const ulonglong2* rc2 = (const ulonglong2*)&relc_s[ch][0];
#pragma unroll
            for (int p2 = 0; p2 < 4; p2++) {
                ulonglong2 rcv = rc2[p2];
                const int p = p2 * 2;
                u64 tv = fmul2(W0, q2[p]);
                tv = ffma2(W1, q2[8 + p], tv);
                tv = ffma2(W2, q2[16 + p], tv);
                tv = ffma2(W3, q2[24 + p], tv);
                acc2[p] = ffma2(rcv.x, tv, acc2[p]);
                u64 tw = fmul2(W0, q2[p + 1]);
                tw = ffma2(W1, q2[8 + p + 1], tw);
                tw = ffma2(W2, q2[16 + p + 1], tw);
                tw = ffma2(W3, q2[24 + p + 1], tw);
                acc2[p + 1] = ffma2(rcv.y, tw, acc2[p + 1]);
            }
        }
        u64* part = (u64*)smemA;
#pragma unroll
        for (int p = 0; p < 8; p++) part[t * 8 + p] = acc2[p];
    }
    __syncthreads();
    // reduce over the 4 e-groups (packed)
    {
        const u64* part = (const u64*)smemA;
        for (int v = t; v < 512; v += 256) {
            const int nbd = v >> 3;
            const int p   = v & 7;
            u64 s = part[nbd * 8 + p];
            s = fadd2(s, part[(64  + nbd) * 8 + p]);
            s = fadd2(s, part[(128 + nbd) * 8 + p]);
            s = fadd2(s, part[(192 + nbd) * 8 + p]);
            ((u64*)&rl_s[nbd >> 4][nbd & 15][0])[p] = s;
        }
    }
    __syncthreads();

    // ---------------- Phase 4: MLP + softmax + attention ----------------
    if (t < 64) {
        const int n = t >> 4;
        const int p = t & 15;
        float h1[16];
#pragma unroll
        for (int h = 0; h < 16; h++) {
            float s = b_sf1[h];
            const float* w1r = w_sf1 + h * 32;
#pragma unroll
            for (int d = 0; d < 16; d++) s += w1r[d] * q_s[n][d][p];
#pragma unroll
            for (int d = 0; d < 16; d++) s += w1r[16 + d] * k_s[n][d][p];
            h1[h] = tanhf(s);
        }
        float lg[16];
        float mx = -1e30f;
#pragma unroll
        for (int m = 0; m < 16; m++) {
            float s = b_sf2[m];
            const float* w2r = w_sf2 + m * 16;
#pragma unroll
            for (int h = 0; h < 16; h++) s += w2r[h] * h1[h];
            s += rl_s[n][m][p];
            lg[m] = s;
            mx = fmaxf(mx, s);
        }
        float den = 0.f;
#pragma unroll
        for (int m = 0; m < 16; m++) { lg[m] = __expf(lg[m] - mx); den += lg[m]; }
        const float inv = 1.0f / den;
#pragma unroll
        for (int dv = 0; dv < 16; dv++) {
            float a = 0.f;
#pragma unroll
            for (int m = 0; m < 16; m++) a += lg[m] * v_s[n][dv][m];
            smemA[(n * 16 + p) * 16 + dv] = a * inv;
        }
    }
    __syncthreads();
    // csum[j = p_lo*16 + dv] = sum over (n, p_hi) of attn[n, p_hi*4+p_lo, dv]
    if (t < 64) {
        const int plo = t >> 4;
        const int dv  = t & 15;
        float s = 0.f;
#pragma unroll
        for (int n2 = 0; n2 < 4; n2++)
#pragma unroll
            for (int ph = 0; ph < 4; ph++)
                s += smemA[(n2 * 16 + ph * 4 + plo) * 16 + dv];
        csum[t] = s;
    }
    __syncthreads();

    // ---------------- Phase 5: projection + sum (coalesced) ----------------
    if (t < 64) {
        const int o = t;
        float acc = 16.0f * b_proj[o];
#pragma unroll 8
        for (int j = 0; j < 64; j++) acc += csum[j] * g_wpt[(j << 6) | o];
        out[b * 65536 + o * 1024 + oy * 32 + ox] = acc;
    }
}

extern "C" void kernel_launch(void* const* d_in, const int* in_sizes, int n_in,
                              void* d_out, int out_size)
{
    (void)in_sizes; (void)n_in; (void)out_size;
    prep_kernel<<<64, 256>>>(
        (const float*)d_in[1],  // wq
        (const float*)d_in[2],  // wk
        (const float*)d_in[3],  // wv
        (const float*)d_in[4],  // w_rel
        (const float*)d_in[5],  // w_deconv
        (const float*)d_in[10]);// w_proj
    selfattn2d_kernel<<<4096, 256>>>(
        (const float*)d_in[0],  // x
        (const float*)d_in[6],  // w_sf1
        (const float*)d_in[7],  // b_sf1
        (const float*)d_in[8],  // w_sf2
        (const float*)d_in[9],  // b_sf2
        (const float*)d_in[11], // b_proj
        (float*)d_out);
}

// round 4
// speedup vs baseline: 1.6313x; 1.6313x over previous
#include <cuda_runtime.h>

// selfAttn2d round 4: conflict-free phase-2 banks (interleaved sp_pad),
// padded q/k/v/rl rows (18) + stride-9 partials to kill store conflicts,
// keep R3's coalesced g_wdt LDG.128 and LDS.128 phase 1.

typedef unsigned long long u64;

__device__ __forceinline__ u64 pack2(float lo, float hi) {
    u64 r; asm("mov.b64 %0,{%1,%2};" : "=l"(r) : "f"(lo), "f"(hi)); return r;
}
__device__ __forceinline__ void unpack2(u64 v, float& lo, float& hi) {
    asm("mov.b64 {%0,%1},%2;" : "=f"(lo), "=f"(hi) : "l"(v));
}
__device__ __forceinline__ u64 ffma2(u64 a, u64 b, u64 c) {
    u64 d; asm("fma.rn.f32x2 %0,%1,%2,%3;" : "=l"(d) : "l"(a), "l"(b), "l"(c)); return d;
}
__device__ __forceinline__ u64 fmul2(u64 a, u64 b) {
    u64 d; asm("mul.rn.f32x2 %0,%1,%2;" : "=l"(d) : "l"(a), "l"(b)); return d;
}
__device__ __forceinline__ u64 fadd2(u64 a, u64 b) {
    u64 d; asm("add.rn.f32x2 %0,%1,%2;" : "=l"(d) : "l"(a), "l"(b)); return d;
}

// Transposed weights (filled by prep_kernel each launch).
__device__ float g_wqt[64 * 64];      // [c][o]
__device__ float g_wkt[64 * 64];
__device__ float g_wvt[64 * 64];
__device__ float g_wpt[64 * 64];      // w_proj [j][o]
__device__ float g_wrt[576 * 64];     // w_rel  [(c*9+u)][ch]
__device__ float g_wdt[64 * 1024];    // w_deconv [ch][n][eg][bd][e]

__global__ void prep_kernel(const float* __restrict__ wq,
                            const float* __restrict__ wk,
                            const float* __restrict__ wv,
                            const float* __restrict__ w_rel,
                            const float* __restrict__ w_deconv,
                            const float* __restrict__ w_proj)
{
    const int i0 = blockIdx.x * blockDim.x + threadIdx.x;
    const int stride = gridDim.x * blockDim.x;
    for (int i = i0; i < 4096; i += stride) {
        int o = i >> 6, c = i & 63;
        int d = (c << 6) | o;
        g_wqt[d] = wq[i];
        g_wkt[d] = wk[i];
        g_wvt[d] = wv[i];
        g_wpt[d] = w_proj[i];
    }
    for (int j = i0; j < 36864; j += stride) {
        int ch = j / 576, r = j - ch * 576;
        g_wrt[r * 64 + ch] = w_rel[j];
    }
    for (int j = i0; j < 65536; j += stride) {
        int ch = j >> 10;
        int rem = j & 1023;
        int n  = rem >> 8;
        int eg = (rem >> 6) & 3;
        int bd = (rem >> 2) & 15;
        int e  = rem & 3;
        g_wdt[j] = w_deconv[ch * 1024 + (n * 16 + eg * 4 + e) * 16 + bd];
    }
}

__global__ __launch_bounds__(256, 2)
void selfattn2d_kernel(const float* __restrict__ x,
                       const float* __restrict__ w_sf1,
                       const float* __restrict__ b_sf1,
                       const float* __restrict__ w_sf2,
                       const float* __restrict__ b_sf2,
                       const float* __restrict__ b_proj,
                       float* __restrict__ out)
{
    // smemA layout (floats):
    //   phases 0-2: sp_pad interleaved [sigma(c)][36] = [0..2303],
    //               sp_lin [c][16] = [2304..3327]
    //   phase 3   : partials, 256 threads * 9 u64 (stride 9) = [0..4607]
    //   phase 4   : attn staging [64][16] = [0..1023]
    __shared__ __align__(16) float smemA[4608];
    __shared__ __align__(16) float q_s[4][16][18];   // [n][e][ac] (padded)
    __shared__ __align__(16) float k_s[4][16][18];
    __shared__ __align__(16) float v_s[4][16][18];
    __shared__ __align__(16) float relc_s[64][16];   // [ch][ac] (16: LDS.128 reads)
    __shared__ __align__(16) float rl_s[4][16][18];  // [n][bd][ac]
    __shared__ float csum[64];

    const int pb = blockIdx.x;
    const int b  = pb >> 10;
    const int oy = (pb >> 5) & 31;
    const int ox = pb & 31;
    const int t  = threadIdx.x;

    // ---------------- Phase 0: load patch ----------------
    {
        const float* xb = x + b * (64 * 64 * 64);
        for (int idx = t; idx < 2304; idx += 256) {
            int c  = idx / 36;
            int r  = idx - c * 36;
            int ii = r / 6;
            int jj = r - ii * 6;
            int gy = oy * 2 + ii - 2;
            int gx = ox * 2 + jj - 2;
            float val = 0.f;
            bool inpatch = (ii >= 1 && ii <= 4 && jj >= 1 && jj <= 4);
            if (inpatch && gy >= 0 && gy < 64 && gx >= 0 && gx < 64)
                val = xb[c * 4096 + gy * 64 + gx];
            // interleaved storage: sigma(c) = (c&15)*4 + (c>>4)
            smemA[((c & 15) * 4 + (c >> 4)) * 36 + r] = val;
            if (inpatch)
                smemA[2304 + c * 16 + (ii - 1) * 4 + (jj - 1)] = val;
        }
    }
    __syncthreads();

    // ---------------- Phase 1: q / k / v (LDS.128 broadcast + f32x2) ----------------
    if (t < 192) {
        const int m = t >> 6;   // 0=q 1=k 2=v
        const int o = t & 63;
        const float* Wt = (m == 0) ? g_wqt : (m == 1) ? g_wkt : g_wvt;
        u64 acc2[8];
#pragma unroll
        for (int p = 0; p < 8; p++) acc2[p] = 0ull;
#pragma unroll 4
        for (int c = 0; c < 64; c++) {
            float w = Wt[(c << 6) | o];
            u64 w2 = pack2(w, w);
            const ulonglong2* row = (const ulonglong2*)(smemA + 2304 + c * 16);
#pragma unroll
            for (int p2 = 0; p2 < 4; p2++) {
                ulonglong2 rv = row[p2];
                acc2[p2 * 2 + 0] = ffma2(w2, rv.x, acc2[p2 * 2 + 0]);
                acc2[p2 * 2 + 1] = ffma2(w2, rv.y, acc2[p2 * 2 + 1]);
            }
        }
        const int n = o >> 4, e = o & 15;
        u64* dst = (m == 0) ? (u64*)&q_s[n][e][0] : (m == 1) ? (u64*)&k_s[n][e][0] : (u64*)&v_s[n][e][0];
        if (m == 0) {
            const u64 s2 = pack2(0.25f, 0.25f);
#pragma unroll
            for (int p = 0; p < 8; p++) dst[p] = fmul2(acc2[p], s2);
        } else {
#pragma unroll
            for (int p = 0; p < 8; p++) dst[p] = acc2[p];
        }
    }

    // ---------------- Phase 2: rel_c (3x3 conv, conflict-free banks) ----------------
    {
        const int ch = t >> 2;
        const int cp = t & 3;
        u64 acc2[8];   // [i][jp]
#pragma unroll
        for (int p = 0; p < 8; p++) acc2[p] = 0ull;
        for (int cc = 0; cc < 16; cc++) {
            // logical channel c = cp*16+cc lives at storage row cc*4+cp
            const float* ebase = smemA + (cc * 4 + cp) * 36;
            const float* wr = g_wrt + (cp * 16 + cc) * 9 * 64 + ch;
            float wf[9];
#pragma unroll
            for (int u = 0; u < 9; u++) wf[u] = wr[u * 64];
            u64 A[6][3], B[6][2];
#pragma unroll
            for (int r = 0; r < 6; r++) {
                const u64* row = (const u64*)(ebase + r * 6);
                A[r][0] = row[0]; A[r][1] = row[1]; A[r][2] = row[2];
                float s0, s1, s2, s3, s4, s5;
                unpack2(A[r][0], s0, s1);
                unpack2(A[r][1], s2, s3);
                unpack2(A[r][2], s4, s5);
                B[r][0] = pack2(s1, s2);
                B[r][1] = pack2(s3, s4);
            }
#pragma unroll
            for (int di = 0; di < 3; di++) {
#pragma unroll
                for (int dj = 0; dj < 3; dj++) {
                    const u64 w2 = pack2(wf[di * 3 + dj], wf[di * 3 + dj]);
#pragma unroll
                    for (int i = 0; i < 4; i++) {
                        const int r = i + di;
                        u64 X0 = (dj == 0) ? A[r][0] : (dj == 1) ? B[r][0] : A[r][1];
                        u64 X1 = (dj == 0) ? A[r][1] : (dj == 1) ? B[r][1] : A[r][2];
                        acc2[i * 2 + 0] = ffma2(w2, X0, acc2[i * 2 + 0]);
                        acc2[i * 2 + 1] = ffma2(w2, X1, acc2[i * 2 + 1]);
                    }
                }
            }
        }
        // reduce the 4 c-quarters (consecutive lanes), packed adds
#pragma unroll
        for (int p = 0; p < 8; p++) {
            u64 v = acc2[p];
            v = fadd2(v, __shfl_down_sync(0xffffffffu, v, 1));
            v = fadd2(v, __shfl_down_sync(0xffffffffu, v, 2));
            if (cp == 0) ((u64*)&relc_s[ch][0])[p] = v;
        }
    }
    __syncthreads();

    // ---------------- Phase 3: fused rel + q contraction ----------------
    {
        const int bd = t & 15;
        const int n  = (t >> 4) & 3;
        const int eg = t >> 6;            // 4 e's per thread
        // preload q pairs (u64 loads; padded rows so broadcast, no conflicts)
        u64 q2[32];
#pragma unroll
        for (int e = 0; e < 4; e++) {
            const u64* qr = (const u64*)&q_s[n][eg * 4 + e][0];
#pragma unroll
            for (int p = 0; p < 8; p++) q2[e * 8 + p] = qr[p];
        }
        u64 acc2[8];
#pragma unroll
        for (int p = 0; p < 8; p++) acc2[p] = 0ull;
        const float4* wd4 = (const float4*)(g_wdt + n * 256 + eg * 64 + bd * 4);
#pragma unroll 2
        for (int ch = 0; ch < 64; ch++) {
            float4 wv4 = wd4[ch * 256];   // coalesced LDG.128
            u64 W0 = pack2(wv4.x, wv4.x), W1 = pack2(wv4.y, wv4.y);
            u64 W2 = pack2(wv4.z, wv4.z), W3 = pack2(wv4.w, wv4.w);
            const ulonglong2* rc2 = (const ulonglong2*)&relc_s[ch][0];
#pragma unroll
            for (int p2 = 0; p2 < 4; p2++) {
                ulonglong2 rcv = rc2[p2];
                const int p = p2 * 2;
                u64 tv = fmul2(W0, q2[p]);
                tv = ffma2(W1, q2[8 + p], tv);
                tv = ffma2(W2, q2[16 + p], tv);
                tv = ffma2(W3, q2[24 + p], tv);
                acc2[p] = ffma2(rcv.x, tv, acc2[p]);
                u64 tw = fmul2(W0, q2[p + 1]);
                tw = ffma2(W1, q2[8 + p + 1], tw);
                tw = ffma2(W2, q2[16 + p + 1], tw);
                tw = ffma2(W3, q2[24 + p + 1], tw);
                acc2[p + 1] = ffma2(rcv.y, tw, acc2[p + 1]);
            }
        }
        u64* part = (u64*)smemA;
#pragma unroll
        for (int p = 0; p < 8; p++) part[t * 9 + p] = acc2[p];   // stride 9: no conflicts
    }
    __syncthreads();
    // reduce over the 4 e-groups (packed)
    {
        const u64* part = (const u64*)smemA;
        for (int v = t; v < 512; v += 256) {
            const int nbd = v >> 3;
            const int p   = v & 7;
            u64 s = part[nbd * 9 + p];
            s = fadd2(s, part[(64  + nbd) * 9 + p]);
            s = fadd2(s, part[(128 + nbd) * 9 + p]);
            s = fadd2(s, part[(192 + nbd) * 9 + p]);
            ((u64*)&rl_s[nbd >> 4][nbd & 15][0])[p] = s;
        }
    }
    __syncthreads();

    // ---------------- Phase 4: MLP + softmax + attention ----------------
    if (t < 64) {
        const int n = t >> 4;
        const int p = t & 15;
        float h1[16];
#pragma unroll
        for (int h = 0; h < 16; h++) {
            float s = b_sf1[h];
            const float* w1r = w_sf1 + h * 32;
#pragma unroll
            for (int d = 0; d < 16; d++) s += w1r[d] * q_s[n][d][p];
#pragma unroll
            for (int d = 0; d < 16; d++) s += w1r[16 + d] * k_s[n][d][p];
            h1[h] = tanhf(s);
        }
        float lg[16];
        float mx = -1e30f;
#pragma unroll
        for (int m = 0; m < 16; m++) {
            float s = b_sf2[m];
            const float* w2r = w_sf2 + m * 16;
#pragma unroll
            for (int h = 0; h < 16; h++) s += w2r[h] * h1[h];
            s += rl_s[n][m][p];
            lg[m] = s;
            mx = fmaxf(mx, s);
        }
        float den = 0.f;
#pragma unroll
        for (int m = 0; m < 16; m++) { lg[m] = __expf(lg[m] - mx); den += lg[m]; }
        const float inv = 1.0f / den;
#pragma unroll
        for (int dv = 0; dv < 16; dv++) {
            float a = 0.f;
#pragma unroll
            for (int m = 0; m < 16; m++) a += lg[m] * v_s[n][dv][m];
            smemA[(n * 16 + p) * 16 + dv] = a * inv;
        }
    }
    __syncthreads();
    // csum[j = p_lo*16 + dv] = sum over (n, p_hi) of attn[n, p_hi*4+p_lo, dv]
    if (t < 64) {
        const int plo = t >> 4;
        const int dv  = t & 15;
        float s = 0.f;
#pragma unroll
        for (int n2 = 0; n2 < 4; n2++)
#pragma unroll
            for (int ph = 0; ph < 4; ph++)
                s += smemA[(n2 * 16 + ph * 4 + plo) * 16 + dv];
        csum[t] = s;
    }
    __syncthreads();

    // ---------------- Phase 5: projection + sum (coalesced) ----------------
    if (t < 64) {
        const int o = t;
        float acc = 16.0f * b_proj[o];
#pragma unroll 8
        for (int j = 0; j < 64; j++) acc += csum[j] * g_wpt[(j << 6) | o];
        out[b * 65536 + o * 1024 + oy * 32 + ox] = acc;
    }
}

extern "C" void kernel_launch(void* const* d_in, const int* in_sizes, int n_in,
                              void* d_out, int out_size)
{
    (void)in_sizes; (void)n_in; (void)out_size;
    prep_kernel<<<64, 256>>>(
        (const float*)d_in[1],  // wq
        (const float*)d_in[2],  // wk
        (const float*)d_in[3],  // wv
        (const float*)d_in[4],  // w_rel
        (const float*)d_in[5],  // w_deconv
        (const float*)d_in[10]);// w_proj
    selfattn2d_kernel<<<4096, 256>>>(
        (const float*)d_in[0],  // x
        (const float*)d_in[6],  // w_sf1
        (const float*)d_in[7],  // b_sf1
        (const float*)d_in[8],  // w_sf2
        (const float*)d_in[9],  // b_sf2
        (const float*)d_in[11], // b_proj
        (float*)d_out);
}

// round 5
// speedup vs baseline: 2.0779x; 1.2738x over previous
#include <cuda_runtime.h>

// selfAttn2d round 5: phase-3 rel/q contraction moved to tensor cores
// (mma.sync.m16n8k8 tf32, per-warp GEMMs, fragment-ordered pre-tf32 B).

typedef unsigned long long u64;

__device__ __forceinline__ u64 pack2(float lo, float hi) {
    u64 r; asm("mov.b64 %0,{%1,%2};" : "=l"(r) : "f"(lo), "f"(hi)); return r;
}
__device__ __forceinline__ void unpack2(u64 v, float& lo, float& hi) {
    asm("mov.b64 {%0,%1},%2;" : "=f"(lo), "=f"(hi) : "l"(v));
}
__device__ __forceinline__ u64 ffma2(u64 a, u64 b, u64 c) {
    u64 d; asm("fma.rn.f32x2 %0,%1,%2,%3;" : "=l"(d) : "l"(a), "l"(b), "l"(c)); return d;
}
__device__ __forceinline__ u64 fmul2(u64 a, u64 b) {
    u64 d; asm("mul.rn.f32x2 %0,%1,%2;" : "=l"(d) : "l"(a), "l"(b)); return d;
}
__device__ __forceinline__ u64 fadd2(u64 a, u64 b) {
    u64 d; asm("add.rn.f32x2 %0,%1,%2;" : "=l"(d) : "l"(a), "l"(b)); return d;
}
__device__ __forceinline__ unsigned int f2tf32(float x) {
    unsigned int r; asm("cvt.rna.tf32.f32 %0, %1;" : "=r"(r) : "f"(x)); return r;
}
__device__ __forceinline__ void mma_tf32(float& d0, float& d1, float& d2, float& d3,
                                         unsigned int a0, unsigned int a1,
                                         unsigned int a2, unsigned int a3,
                                         unsigned int b0, unsigned int b1) {
    asm("mma.sync.aligned.m16n8k8.row.col.f32.tf32.tf32.f32 "
        "{%0,%1,%2,%3},{%4,%5,%6,%7},{%8,%9},{%0,%1,%2,%3};"
        : "+f"(d0), "+f"(d1), "+f"(d2), "+f"(d3)
        : "r"(a0), "r"(a1), "r"(a2), "r"(a3), "r"(b0), "r"(b1));
}

// Transposed weights (filled by prep_kernel each launch).
__device__ float g_wqt[64 * 64];      // [c][o]
__device__ float g_wkt[64 * 64];
__device__ float g_wvt[64 * 64];
__device__ float g_wpt[64 * 64];      // w_proj [j][o]
__device__ float g_wrt[576 * 64];     // w_rel  [(c*9+u)][ch]
// w_deconv, tf32-rounded, mma-B-fragment order:
//   g_wd2[ ((ch*4 + n)*2 + h)*128 + lane*4 + v ]
//   e  = h*8 + (lane&3) + (v&1)*4, bd = (lane>>2) + (v>>1)*8
__device__ float g_wd2[64 * 1024];

__global__ void prep_kernel(const float* __restrict__ wq,
                            const float* __restrict__ wk,
                            const float* __restrict__ wv,
                            const float* __restrict__ w_rel,
                            const float* __restrict__ w_deconv,
                            const float* __restrict__ w_proj)
{
    const int i0 = blockIdx.x * blockDim.x + threadIdx.x;
    const int stride = gridDim.x * blockDim.x;
    for (int i = i0; i < 4096; i += stride) {
        int o = i >> 6, c = i & 63;
        int d = (c << 6) | o;
        g_wqt[d] = wq[i];
        g_wkt[d] = wk[i];
        g_wvt[d] = wv[i];
        g_wpt[d] = w_proj[i];
    }
    for (int j = i0; j < 36864; j += stride) {
        int ch = j / 576, r = j - ch * 576;
        g_wrt[r * 64 + ch] = w_rel[j];
    }
    for (int j = i0; j < 65536; j += stride) {
        int v    = j & 3;
        int lane = (j >> 2) & 31;
        int h    = (j >> 7) & 1;
        int n    = (j >> 8) & 3;
        int ch   = j >> 10;
        int e  = h * 8 + (lane & 3) + (v & 1) * 4;
        int bd = (lane >> 2) + (v >> 1) * 8;
        float w = w_deconv[ch * 1024 + (n * 16 + e) * 16 + bd];
        unsigned int tw = f2tf32(w);
        g_wd2[j] = __uint_as_float(tw);
    }
}

__global__ __launch_bounds__(256, 2)
void selfattn2d_kernel(const float* __restrict__ x,
                       const float* __restrict__ w_sf1,
                       const float* __restrict__ b_sf1,
                       const float* __restrict__ w_sf2,
                       const float* __restrict__ b_sf2,
                       const float* __restrict__ b_proj,
                       float* __restrict__ out)
{
    // smemA layout (floats):
    //   phases 0-2: sp_pad interleaved [sigma(c)][36] = [0..2303],
    //               sp_lin [c][16] = [2304..3327]
    //   phase 3   : rl partials rlp[w][16ac][18] = [0..2303] (w*288)
    //   phase 4   : attn staging [64][16] = [2304..3327]
    __shared__ __align__(16) float smemA[4608];
    __shared__ __align__(16) float q_s[4][16][18];   // [n][e][ac]
    __shared__ __align__(16) float k_s[4][16][18];
    __shared__ __align__(16) float v_s[4][16][18];
    __shared__ __align__(16) float relc_s[64][16];   // [ch][ac]
    __shared__ float csum[64];

    const int pb = blockIdx.x;
    const int b  = pb >> 10;
    const int oy = (pb >> 5) & 31;
    const int ox = pb & 31;
    const int t  = threadIdx.x;

    // ---------------- Phase 0: load patch ----------------
    {
        const float* xb = x + b * (64 * 64 * 64);
        for (int idx = t; idx < 2304; idx += 256) {
            int c  = idx / 36;
            int r  = idx - c * 36;
            int ii = r / 6;
            int jj = r - ii * 6;
            int gy = oy * 2 + ii - 2;
            int gx = ox * 2 + jj - 2;
            float val = 0.f;
            bool inpatch = (ii >= 1 && ii <= 4 && jj >= 1 && jj <= 4);
            if (inpatch && gy >= 0 && gy < 64 && gx >= 0 && gx < 64)
                val = xb[c * 4096 + gy * 64 + gx];
            smemA[((c & 15) * 4 + (c >> 4)) * 36 + r] = val;   // interleaved
            if (inpatch)
                smemA[2304 + c * 16 + (ii - 1) * 4 + (jj - 1)] = val;
        }
    }
    __syncthreads();

    // ---------------- Phase 1: q / k / v ----------------
    if (t < 192) {
        const int m = t >> 6;   // 0=q 1=k 2=v
        const int o = t & 63;
        const float* Wt = (m == 0) ? g_wqt : (m == 1) ? g_wkt : g_wvt;
        u64 acc2[8];
#pragma unroll
        for (int p = 0; p < 8; p++) acc2[p] = 0ull;
#pragma unroll 4
        for (int c = 0; c < 64; c++) {
            float w = Wt[(c << 6) | o];
            u64 w2 = pack2(w, w);
            const ulonglong2* row = (const ulonglong2*)(smemA + 2304 + c * 16);
#pragma unroll
            for (int p2 = 0; p2 < 4; p2++) {
                ulonglong2 rv = row[p2];
                acc2[p2 * 2 + 0] = ffma2(w2, rv.x, acc2[p2 * 2 + 0]);
                acc2[p2 * 2 + 1] = ffma2(w2, rv.y, acc2[p2 * 2 + 1]);
            }
        }
        const int n = o >> 4, e = o & 15;
        u64* dst = (m == 0) ? (u64*)&q_s[n][e][0] : (m == 1) ? (u64*)&k_s[n][e][0] : (u64*)&v_s[n][e][0];
        if (m == 0) {
            const u64 s2 = pack2(0.25f, 0.25f);
#pragma unroll
            for (int p = 0; p < 8; p++) dst[p] = fmul2(acc2[p], s2);
        } else {
#pragma unroll
            for (int p = 0; p < 8; p++) dst[p] = acc2[p];
        }
    }

    // ---------------- Phase 2: rel_c (3x3 conv, conflict-free) ----------------
    {
        const int ch = t >> 2;
        const int cp = t & 3;
        u64 acc2[8];
#pragma unroll
        for (int p = 0; p < 8; p++) acc2[p] = 0ull;
        for (int cc = 0; cc < 16; cc++) {
            const float* ebase = smemA + (cc * 4 + cp) * 36;
            const float* wr = g_wrt + (cp * 16 + cc) * 9 * 64 + ch;
            float wf[9];
#pragma unroll
            for (int u = 0; u < 9; u++) wf[u] = wr[u * 64];
            u64 A[6][3], B[6][2];
#pragma unroll
            for (int r = 0; r < 6; r++) {
                const u64* row = (const u64*)(ebase + r * 6);
                A[r][0] = row[0]; A[r][1] = row[1]; A[r][2] = row[2];
                float s0, s1, s2, s3, s4, s5;
                unpack2(A[r][0], s0, s1);
                unpack2(A[r][1], s2, s3);
                unpack2(A[r][2], s4, s5);
                B[r][0] = pack2(s1, s2);
                B[r][1] = pack2(s3, s4);
            }
#pragma unroll
            for (int di = 0; di < 3; di++) {
#pragma unroll
                for (int dj = 0; dj < 3; dj++) {
                    const u64 w2 = pack2(wf[di * 3 + dj], wf[di * 3 + dj]);
#pragma unroll
                    for (int i = 0; i < 4; i++) {
                        const int r = i + di;
                        u64 X0 = (dj == 0) ? A[r][0] : (dj == 1) ? B[r][0] : A[r][1];
                        u64 X1 = (dj == 0) ? A[r][1] : (dj == 1) ? B[r][1] : A[r][2];
                        acc2[i * 2 + 0] = ffma2(w2, X0, acc2[i * 2 + 0]);
                        acc2[i * 2 + 1] = ffma2(w2, X1, acc2[i * 2 + 1]);
                    }
                }
            }
        }
#pragma unroll
        for (int p = 0; p < 8; p++) {
            u64 v = acc2[p];
            v = fadd2(v, __shfl_down_sync(0xffffffffu, v, 1));
            v = fadd2(v, __shfl_down_sync(0xffffffffu, v, 2));
            if (cp == 0) ((u64*)&relc_s[ch][0])[p] = v;
        }
    }
    __syncthreads();

    // ---------------- Phase 3: rel+q contraction on tensor cores ----------------
    // warp w: n = w>>1, ch range = (w&1)*32..+31.
    // C[16ac x 16bd] += A[ac,(ch,e)] * B[(ch,e),bd],
    //   A[ac,k] = relc[ch,ac] * q[n,e,ac]  (built per k-octet, tf32-rounded)
    {
        const int lane = t & 31;
        const int w    = t >> 5;
        const int n    = w >> 1;
        const int ch0  = (w & 1) * 32;
        const int g    = lane >> 2;   // 0..7
        const int tg   = lane & 3;    // 0..3

        // hoist q: lane needs e in {tg, tg+4, tg+8, tg+12}, rows g and g+8
        float qa[4], qb[4];
#pragma unroll
        for (int j = 0; j < 4; j++) {
            qa[j] = q_s[n][tg + 4 * j][g];
            qb[j] = q_s[n][tg + 4 * j][g + 8];
        }
        float d0 = 0.f, d1 = 0.f, d2 = 0.f, d3 = 0.f;   // bd 0-7
        float e0 = 0.f, e1 = 0.f, e2 = 0.f, e3 = 0.f;   // bd 8-15
        const float4* wd4 = (const float4*)g_wd2;
#pragma unroll 4
        for (int ch = ch0; ch < ch0 + 32; ch++) {
            const float r0 = relc_s[ch][g];
            const float r1 = relc_s[ch][g + 8];
#pragma unroll
            for (int h = 0; h < 2; h++) {
                unsigned int a0 = f2tf32(r0 * qa[2 * h + 0]);
                unsigned int a1 = f2tf32(r1 * qb[2 * h + 0]);
                unsigned int a2 = f2tf32(r0 * qa[2 * h + 1]);
                unsigned int a3 = f2tf32(r1 * qb[2 * h + 1]);
                float4 B4 = wd4[((ch * 4 + n) * 2 + h) * 32 + lane];
                mma_tf32(d0, d1, d2, d3, a0, a1, a2, a3,
                         __float_as_uint(B4.x), __float_as_uint(B4.y));
                mma_tf32(e0, e1, e2, e3, a0, a1, a2, a3,
                         __float_as_uint(B4.z), __float_as_uint(B4.w));
            }
        }
        // store C partials: rlp[w][ac][18], C[row=ac][col=bd]
        float* rp = smemA + w * 288;
        *(float2*)(rp + g * 18 + 2 * tg)            = make_float2(d0, d1);
        *(float2*)(rp + (g + 8) * 18 + 2 * tg)      = make_float2(d2, d3);
        *(float2*)(rp + g * 18 + 8 + 2 * tg)        = make_float2(e0, e1);
        *(float2*)(rp + (g + 8) * 18 + 8 + 2 * tg)  = make_float2(e2, e3);
    }
    __syncthreads();

    // ---------------- Phase 4: MLP + softmax + attention ----------------
    if (t < 64) {
        const int n = t >> 4;
        const int p = t & 15;
        float h1[16];
#pragma unroll
        for (int h = 0; h < 16; h++) {
            float s = b_sf1[h];
            const float* w1r = w_sf1 + h * 32;
#pragma unroll
            for (int d = 0; d < 16; d++) s += w1r[d] * q_s[n][d][p];
#pragma unroll
            for (int d = 0; d < 16; d++) s += w1r[16 + d] * k_s[n][d][p];
            h1[h] = tanhf(s);
        }
        const float* rp0 = smemA + (2 * n) * 288 + p * 18;
        const float* rp1 = smemA + (2 * n + 1) * 288 + p * 18;
        float lg[16];
        float mx = -1e30f;
#pragma unroll
        for (int m = 0; m < 16; m++) {
            float s = b_sf2[m];
            const float* w2r = w_sf2 + m * 16;
#pragma unroll
            for (int h = 0; h < 16; h++) s += w2r[h] * h1[h];
            s += rp0[m] + rp1[m];        // rel_logits[n][query=p][key=m]
            lg[m] = s;
            mx = fmaxf(mx, s);
        }
        float den = 0.f;
#pragma unroll
        for (int m = 0; m < 16; m++) { lg[m] = __expf(lg[m] - mx); den += lg[m]; }
        const float inv = 1.0f / den;
#pragma unroll
        for (int dv = 0; dv < 16; dv++) {
            float a = 0.f;
#pragma unroll
            for (int m = 0; m < 16; m++) a += lg[m] * v_s[n][dv][m];
            smemA[2304 + (n * 16 + p) * 16 + dv] = a * inv;
        }
    }
    __syncthreads();
    // csum[j = p_lo*16 + dv] = sum over (n, p_hi) of attn[n, p_hi*4+p_lo, dv]
    if (t < 64) {
        const int plo = t >> 4;
        const int dv  = t & 15;
        float s = 0.f;
#pragma unroll
        for (int n2 = 0; n2 < 4; n2++)
#pragma unroll
            for (int ph = 0; ph < 4; ph++)
                s += smemA[2304 + (n2 * 16 + ph * 4 + plo) * 16 + dv];
        csum[t] = s;
    }
    __syncthreads();

    // ---------------- Phase 5: projection + sum ----------------
    if (t < 64) {
        const int o = t;
        float acc = 16.0f * b_proj[o];
#pragma unroll 8
        for (int j = 0; j < 64; j++) acc += csum[j] * g_wpt[(j << 6) | o];
        out[b * 65536 + o * 1024 + oy * 32 + ox] = acc;
    }
}

extern "C" void kernel_launch(void* const* d_in, const int* in_sizes, int n_in,
                              void* d_out, int out_size)
{
    (void)in_sizes; (void)n_in; (void)out_size;
    prep_kernel<<<64, 256>>>(
        (const float*)d_in[1],  // wq
        (const float*)d_in[2],  // wk
        (const float*)d_in[3],  // wv
        (const float*)d_in[4],  // w_rel
        (const float*)d_in[5],  // w_deconv
        (const float*)d_in[10]);// w_proj
    selfattn2d_kernel<<<4096, 256>>>(
        (const float*)d_in[0],  // x
        (const float*)d_in[6],  // w_sf1
        (const float*)d_in[7],  // b_sf1
        (const float*)d_in[8],  // w_sf2
        (const float*)d_in[9],  // b_sf2
        (const float*)d_in[11], // b_proj
        (float*)d_out);
}

// round 6
// speedup vs baseline: 3.2797x; 1.5784x over previous
#include <cuda_runtime.h>

// selfAttn2d round 6: all three GEMM phases (qkv, conv, rel-contraction) on
// tensor cores (mma.sync m16n8k8 tf32); phase 4 parallelized to 128 threads.

__device__ __forceinline__ unsigned int f2tf32(float x) {
    unsigned int r; asm("cvt.rna.tf32.f32 %0, %1;" : "=r"(r) : "f"(x)); return r;
}
__device__ __forceinline__ unsigned int fu(float x) { return __float_as_uint(x); }
__device__ __forceinline__ void mma_tf32(float& d0, float& d1, float& d2, float& d3,
                                         unsigned int a0, unsigned int a1,
                                         unsigned int a2, unsigned int a3,
                                         unsigned int b0, unsigned int b1) {
    asm("mma.sync.aligned.m16n8k8.row.col.f32.tf32.tf32.f32 "
        "{%0,%1,%2,%3},{%4,%5,%6,%7},{%8,%9},{%0,%1,%2,%3};"
        : "+f"(d0), "+f"(d1), "+f"(d2), "+f"(d3)
        : "r"(a0), "r"(a1), "r"(a2), "r"(a3), "r"(b0), "r"(b1));
}

// Prepped tables (filled by prep_kernel each launch).
__device__ float g_wa1[12 * 8 * 32 * 4];   // qkv A-frags  [mt][oct][lane][r], tf32
__device__ float g_wa2[4 * 72 * 32 * 4];   // conv A-frags [mt][oct][lane][r], tf32 (k = u*64+c)
__device__ float g_wd2[64 * 1024];         // w_deconv B-frags (R5 layout), tf32
__device__ float g_wpt[64 * 64];           // w_proj [j][o]

__global__ void prep_kernel(const float* __restrict__ wq,
                            const float* __restrict__ wk,
                            const float* __restrict__ wv,
                            const float* __restrict__ w_rel,
                            const float* __restrict__ w_deconv,
                            const float* __restrict__ w_proj)
{
    const int i0 = blockIdx.x * blockDim.x + threadIdx.x;
    const int stride = gridDim.x * blockDim.x;
    for (int i = i0; i < 4096; i += stride) {
        int o = i >> 6, c = i & 63;
        g_wpt[(c << 6) | o] = w_proj[i];
    }
    // qkv A-frags: m16n8k8 row-major A; tile mt: rows = (mt&3)*16.., k = c (0..63)
    for (int j = i0; j < 12288; j += stride) {
        int r = j & 3, lane = (j >> 2) & 31, oct = (j >> 7) & 7, mt = j >> 10;
        int row = (lane >> 2) + ((r & 1) << 3);
        int k   = oct * 8 + (lane & 3) + ((r >> 1) << 2);
        const float* W = (mt < 4) ? wq : (mt < 8) ? wk : wv;
        g_wa1[j] = __uint_as_float(f2tf32(W[((mt & 3) * 16 + row) * 64 + k]));
    }
    // conv A-frags: A[ch][k=u*64+c] = w_rel[ch][c][u]; tile mt: ch = mt*16..
    for (int j = i0; j < 36864; j += stride) {
        int r = j & 3, lane = (j >> 2) & 31;
        int mo = j >> 7;                 // mt*72 + oct
        int mt = mo / 72, oct = mo - mt * 72;
        int u = oct >> 3, jj = oct & 7;
        int ch = mt * 16 + (lane >> 2) + ((r & 1) << 3);
        int c  = jj * 8 + (lane & 3) + ((r >> 1) << 2);
        g_wa2[j] = __uint_as_float(f2tf32(w_rel[ch * 576 + c * 9 + u]));
    }
    // w_deconv B-frags (phase 3), R5 layout
    for (int j = i0; j < 65536; j += stride) {
        int v    = j & 3;
        int lane = (j >> 2) & 31;
        int h    = (j >> 7) & 1;
        int n    = (j >> 8) & 3;
        int ch   = j >> 10;
        int e  = h * 8 + (lane & 3) + (v & 1) * 4;
        int bd = (lane >> 2) + (v >> 1) * 8;
        g_wd2[j] = __uint_as_float(f2tf32(w_deconv[ch * 1024 + (n * 16 + e) * 16 + bd]));
    }
}

__global__ __launch_bounds__(256, 2)
void selfattn2d_kernel(const float* __restrict__ x,
                       const float* __restrict__ w_sf1,
                       const float* __restrict__ b_sf1,
                       const float* __restrict__ w_sf2,
                       const float* __restrict__ b_sf2,
                       const float* __restrict__ b_proj,
                       float* __restrict__ out)
{
    // smemA (floats), region reuse:
    //   phase 0-2: sp_pad interleaved [sigma(c)][37] = [0..2367] (tf32-rounded)
    //              sp_lin [c][24] = [2368..3903]              (tf32-rounded)
    //   phase 2  : rcp partials [8 warps][16][18] = [0..2303]
    //   phase 3  : rlp partials [8 warps][16][18] = [0..2303]
    //   phase 4  : hbuf/attn [2304..3327], wbuf [3328..4351]
    __shared__ __align__(16) float smemA[4608];
    __shared__ __align__(16) float q_s[4][16][18];   // [n][e][ac]
    __shared__ __align__(16) float k_s[4][16][18];
    __shared__ __align__(16) float v_s[4][16][18];
    __shared__ __align__(16) float relc_s[64][16];   // [ch][ac]
    __shared__ float csum[64];

    const int pb = blockIdx.x;
    const int b  = pb >> 10;
    const int oy = (pb >> 5) & 31;
    const int ox = pb & 31;
    const int t  = threadIdx.x;
    const int lane = t & 31;
    const int w    = t >> 5;

    // ---------------- Phase 0: load patch, tf32-round once ----------------
    {
        const float* xb = x + b * (64 * 64 * 64);
        for (int idx = t; idx < 2304; idx += 256) {
            int c  = idx / 36;
            int r  = idx - c * 36;
            int ii = r / 6;
            int jj = r - ii * 6;
            int gy = oy * 2 + ii - 2;
            int gx = ox * 2 + jj - 2;
            float val = 0.f;
            bool inpatch = (ii >= 1 && ii <= 4 && jj >= 1 && jj <= 4);
            if (inpatch && gy >= 0 && gy < 64 && gx >= 0 && gx < 64)
                val = xb[c * 4096 + gy * 64 + gx];
            val = __uint_as_float(f2tf32(val));
            smemA[((c & 15) * 4 + (c >> 4)) * 37 + r] = val;    // interleaved, stride 37
            if (inpatch)
                smemA[2368 + c * 24 + (ii - 1) * 4 + (jj - 1)] = val;  // stride 24
        }
    }
    __syncthreads();

    // ---------------- Phase 1: q/k/v on tensor cores ----------------
    // 12 m16-tiles (0-3:q heads, 4-7:k, 8-11:v). warp w: tile w; w>=4 also tile w+4.
    {
        const float* spl = smemA + 2368;
        const int base0 = (lane & 3) * 24 + (lane >> 2);
        const int row = lane >> 2, col = 2 * (lane & 3);
#pragma unroll
        for (int ti = 0; ti < 2; ti++) {
            int mt = (ti == 0) ? w : (w + 4);
            if (ti == 1 && w < 4) break;
            float d0 = 0.f, d1 = 0.f, d2 = 0.f, d3 = 0.f;
            float e0 = 0.f, e1 = 0.f, e2 = 0.f, e3 = 0.f;
            const float4* wa = ((const float4*)g_wa1) + mt * 256 + lane;
#pragma unroll
            for (int oct = 0; oct < 8; oct++) {
                float4 A4 = wa[oct * 32];
                const float* bp = spl + base0 + oct * 192;
                float b0 = bp[0], b1 = bp[96];       // ac = lane>>2
                float c0 = bp[8], c1 = bp[104];      // ac + 8
                mma_tf32(d0, d1, d2, d3, fu(A4.x), fu(A4.y), fu(A4.z), fu(A4.w), fu(b0), fu(b1));
                mma_tf32(e0, e1, e2, e3, fu(A4.x), fu(A4.y), fu(A4.z), fu(A4.w), fu(c0), fu(c1));
            }
            float sc = (mt < 4) ? 0.25f : 1.0f;
            float* dst = (mt < 4) ? &q_s[mt][0][0]
                       : (mt < 8) ? &k_s[mt - 4][0][0]
                                  : &v_s[mt - 8][0][0];
            *(float2*)(dst + row * 18 + col)           = make_float2(d0 * sc, d1 * sc);
            *(float2*)(dst + (row + 8) * 18 + col)     = make_float2(d2 * sc, d3 * sc);
            *(float2*)(dst + row * 18 + col + 8)       = make_float2(e0 * sc, e1 * sc);
            *(float2*)(dst + (row + 8) * 18 + col + 8) = make_float2(e2 * sc, e3 * sc);
        }
    }

    // ---------------- Phase 2: rel_c conv on tensor cores ----------------
    // warp w: ch-tile mt = w&3, u-half = w>>2 (u 0..4 / 5..8). K order k = u*64+c.
    {
        const int mt = w & 3, halfk = w >> 2;
        float d0 = 0.f, d1 = 0.f, d2 = 0.f, d3 = 0.f;
        float e0 = 0.f, e1 = 0.f, e2 = 0.f, e3 = 0.f;
        const float4* wa = ((const float4*)g_wa2) + mt * 2304 + lane;
        const int q37 = (lane & 3) * 148;            // (lane&3)*4*37
        const int ac = lane >> 2;
        const int Pa = (ac >> 2) * 6 + (ac & 3);
#pragma unroll
        for (int u = 0; u < 9; u++) {
            bool mine = (halfk == 0) ? (u < 5) : (u >= 5);
            if (mine) {
                const int P = Pa + (u / 3) * 6 + (u % 3);
#pragma unroll
                for (int j = 0; j < 8; j++) {
                    float4 A4 = wa[(u * 8 + j) * 32];
                    int base = q37 + (j & 1) * 1184 + (j >> 1) * 37 + P;
                    float b0 = smemA[base],      b1 = smemA[base + 592];
                    float c0 = smemA[base + 12], c1 = smemA[base + 604];
                    mma_tf32(d0, d1, d2, d3, fu(A4.x), fu(A4.y), fu(A4.z), fu(A4.w), fu(b0), fu(b1));
                    mma_tf32(e0, e1, e2, e3, fu(A4.x), fu(A4.y), fu(A4.z), fu(A4.w), fu(c0), fu(c1));
                }
            }
        }
        __syncthreads();                 // all sp_pad / sp_lin reads complete
        float* rp = smemA + w * 288;     // rcp partials [16][18]
        const int row = lane >> 2, col = 2 * (lane & 3);
        *(float2*)(rp + row * 18 + col)           = make_float2(d0, d1);
        *(float2*)(rp + (row + 8) * 18 + col)     = make_float2(d2, d3);
        *(float2*)(rp + row * 18 + col + 8)       = make_float2(e0, e1);
        *(float2*)(rp + (row + 8) * 18 + col + 8) = make_float2(e2, e3);
    }
    __syncthreads();
    // reduce the two u-halves into relc_s
    {
        const int ch = t >> 2, a0 = (t & 3) * 4;
        const int mt2 = ch >> 4, r2 = ch & 15;
        const float* pa = smemA + mt2 * 288 + r2 * 18 + a0;
        const float* pb = pa + 4 * 288;
#pragma unroll
        for (int kk = 0; kk < 4; kk++) relc_s[ch][a0 + kk] = pa[kk] + pb[kk];
    }
    __syncthreads();

    // ---------------- Phase 3: rel+q contraction on tensor cores (as R5) ----------------
    {
        const int n    = w >> 1;
        const int ch0  = (w & 1) * 32;
        const int g    = lane >> 2;
        const int tg   = lane & 3;
        float qa[4], qb[4];
#pragma unroll
        for (int j = 0; j < 4; j++) {
            qa[j] = q_s[n][tg + 4 * j][g];
            qb[j] = q_s[n][tg + 4 * j][g + 8];
        }
        float d0 = 0.f, d1 = 0.f, d2 = 0.f, d3 = 0.f;
        float e0 = 0.f, e1 = 0.f, e2 = 0.f, e3 = 0.f;
        const float4* wd4 = (const float4*)g_wd2;
#pragma unroll 4
        for (int ch = ch0; ch < ch0 + 32; ch++) {
            const float r0 = relc_s[ch][g];
            const float r1 = relc_s[ch][g + 8];
#pragma unroll
            for (int h = 0; h < 2; h++) {
                unsigned int a0 = f2tf32(r0 * qa[2 * h + 0]);
                unsigned int a1 = f2tf32(r1 * qb[2 * h + 0]);
                unsigned int a2 = f2tf32(r0 * qa[2 * h + 1]);
                unsigned int a3 = f2tf32(r1 * qb[2 * h + 1]);
                float4 B4 = wd4[((ch * 4 + n) * 2 + h) * 32 + lane];
                mma_tf32(d0, d1, d2, d3, a0, a1, a2, a3, fu(B4.x), fu(B4.y));
                mma_tf32(e0, e1, e2, e3, a0, a1, a2, a3, fu(B4.z), fu(B4.w));
            }
        }
        float* rp = smemA + w * 288;   // rlp partials [ac][18]
        *(float2*)(rp + g * 18 + 2 * tg)           = make_float2(d0, d1);
        *(float2*)(rp + (g + 8) * 18 + 2 * tg)     = make_float2(d2, d3);
        *(float2*)(rp + g * 18 + 8 + 2 * tg)       = make_float2(e0, e1);
        *(float2*)(rp + (g + 8) * 18 + 8 + 2 * tg) = make_float2(e2, e3);
    }
    __syncthreads();

    // ---------------- Phase 4: MLP + softmax + attention (128 threads) ----------------
    if (t < 128) {
        const int n = t >> 5, p = (t >> 1) & 15, hf = t & 1;
        const float* qc = &q_s[n][0][p];
        const float* kc = &k_s[n][0][p];
        float h1v[8];
#pragma unroll
        for (int hh = 0; hh < 8; hh++) {
            int h = hf * 8 + hh;
            float s = b_sf1[h];
            const float* w1r = w_sf1 + h * 32;
#pragma unroll
            for (int d = 0; d < 16; d++) s += w1r[d] * qc[d * 18];
#pragma unroll
            for (int d = 0; d < 16; d++) s += w1r[16 + d] * kc[d * 18];
            h1v[hh] = tanhf(s);
        }
        float* hb = smemA + 2304 + (n * 16 + p) * 16 + hf * 8;
        *(float4*)hb       = make_float4(h1v[0], h1v[1], h1v[2], h1v[3]);
        *(float4*)(hb + 4) = make_float4(h1v[4], h1v[5], h1v[6], h1v[7]);
    }
    __syncthreads();
    if (t < 128) {
        const int n = t >> 5, p = (t >> 1) & 15, hf = t & 1;
        float hv[16];
        const float4* hb4 = (const float4*)(smemA + 2304 + (n * 16 + p) * 16);
#pragma unroll
        for (int i4 = 0; i4 < 4; i4++) {
            float4 v4 = hb4[i4];
            hv[4 * i4] = v4.x; hv[4 * i4 + 1] = v4.y; hv[4 * i4 + 2] = v4.z; hv[4 * i4 + 3] = v4.w;
        }
        const float* rp0 = smemA + (2 * n) * 288 + p * 18;
        const float* rp1 = rp0 + 288;
        float lg[8];
        float mx = -1e30f;
#pragma unroll
        for (int mm = 0; mm < 8; mm++) {
            int m = hf * 8 + mm;
            float s = b_sf2[m];
            const float* w2r = w_sf2 + m * 16;
#pragma unroll
            for (int h = 0; h < 16; h++) s += w2r[h] * hv[h];
            s += rp0[m] + rp1[m];
            lg[mm] = s;
            mx = fmaxf(mx, s);
        }
        mx = fmaxf(mx, __shfl_xor_sync(0xffffffffu, mx, 1));
        float den = 0.f;
#pragma unroll
        for (int mm = 0; mm < 8; mm++) { lg[mm] = __expf(lg[mm] - mx); den += lg[mm]; }
        den += __shfl_xor_sync(0xffffffffu, den, 1);
        const float inv = 1.0f / den;
        float* wb = smemA + 3328 + (n * 16 + p) * 16 + hf * 8;
        *(float4*)wb       = make_float4(lg[0] * inv, lg[1] * inv, lg[2] * inv, lg[3] * inv);
        *(float4*)(wb + 4) = make_float4(lg[4] * inv, lg[5] * inv, lg[6] * inv, lg[7] * inv);
    }
    __syncthreads();
    if (t < 128) {
        const int n = t >> 5, p = (t >> 1) & 15, hf = t & 1;
        float wv_[16];
        const float4* wb4 = (const float4*)(smemA + 3328 + (n * 16 + p) * 16);
#pragma unroll
        for (int i4 = 0; i4 < 4; i4++) {
            float4 v4 = wb4[i4];
            wv_[4 * i4] = v4.x; wv_[4 * i4 + 1] = v4.y; wv_[4 * i4 + 2] = v4.z; wv_[4 * i4 + 3] = v4.w;
        }
        float av[8];
#pragma unroll
        for (int dd = 0; dd < 8; dd++) {
            int dv = hf * 8 + dd;
            const float2* vr = (const float2*)&v_s[n][dv][0];
            float a = 0.f;
#pragma unroll
            for (int m2 = 0; m2 < 8; m2++) {
                float2 vv = vr[m2];
                a += wv_[2 * m2] * vv.x + wv_[2 * m2 + 1] * vv.y;
            }
            av[dd] = a;
        }
        float* ab = smemA + 2304 + (n * 16 + p) * 16 + hf * 8;
        *(float4*)ab       = make_float4(av[0], av[1], av[2], av[3]);
        *(float4*)(ab + 4) = make_float4(av[4], av[5], av[6], av[7]);
    }
    __syncthreads();
    // csum[j = p_lo*16 + dv] = sum over (n, p_hi) of attn[n, p_hi*4+p_lo, dv]
    if (t < 64) {
        const int plo = t >> 4;
        const int dv  = t & 15;
        float s = 0.f;
#pragma unroll
        for (int n2 = 0; n2 < 4; n2++)
#pragma unroll
            for (int ph = 0; ph < 4; ph++)
                s += smemA[2304 + (n2 * 16 + ph * 4 + plo) * 16 + dv];
        csum[t] = s;
    }
    __syncthreads();

    // ---------------- Phase 5: projection + sum ----------------
    if (t < 64) {
        const int o = t;
        float acc = 16.0f * b_proj[o];
#pragma unroll 8
        for (int j = 0; j < 64; j++) acc += csum[j] * g_wpt[(j << 6) | o];
        out[b * 65536 + o * 1024 + oy * 32 + ox] = acc;
    }
}

extern "C" void kernel_launch(void* const* d_in, const int* in_sizes, int n_in,
                              void* d_out, int out_size)
{
    (void)in_sizes; (void)n_in; (void)out_size;
    prep_kernel<<<64, 256>>>(
        (const float*)d_in[1],  // wq
        (const float*)d_in[2],  // wk
        (const float*)d_in[3],  // wv
        (const float*)d_in[4],  // w_rel
        (const float*)d_in[5],  // w_deconv
        (const float*)d_in[10]);// w_proj
    selfattn2d_kernel<<<4096, 256>>>(
        (const float*)d_in[0],  // x
        (const float*)d_in[6],  // w_sf1
        (const float*)d_in[7],  // b_sf1
        (const float*)d_in[8],  // w_sf2
        (const float*)d_in[9],  // b_sf2
        (const float*)d_in[11], // b_proj
        (float*)d_out);
}

// round 8
// speedup vs baseline: 3.5011x; 1.0675x over previous
#include <cuda_runtime.h>

// selfAttn2d round 8 (= round 7 resubmit after infra failure):
// 2 patches per CTA (fragment-table LDGs serve both patches), relc transposed
// for broadcast LDS.128 in P3, tail parallelized across 256 threads.

__device__ __forceinline__ unsigned int f2tf32(float x) {
    unsigned int r; asm("cvt.rna.tf32.f32 %0, %1;" : "=r"(r) : "f"(x)); return r;
}
__device__ __forceinline__ unsigned int fu(float x) { return __float_as_uint(x); }
__device__ __forceinline__ void mma_tf32(float& d0, float& d1, float& d2, float& d3,
                                         unsigned int a0, unsigned int a1,
                                         unsigned int a2, unsigned int a3,
                                         unsigned int b0, unsigned int b1) {
    asm("mma.sync.aligned.m16n8k8.row.col.f32.tf32.tf32.f32 "
        "{%0,%1,%2,%3},{%4,%5,%6,%7},{%8,%9},{%0,%1,%2,%3};"
        : "+f"(d0), "+f"(d1), "+f"(d2), "+f"(d3)
        : "r"(a0), "r"(a1), "r"(a2), "r"(a3), "r"(b0), "r"(b1));
}

// Prepped tables (filled by prep_kernel each launch).
__device__ float g_wa1[12 * 8 * 32 * 4];   // qkv A-frags  [mt][oct][lane][r], tf32
__device__ float g_wa2[4 * 72 * 32 * 4];   // conv A-frags [mt][oct][lane][r], tf32
__device__ float g_wd2[64 * 1024];         // w_deconv B-frags, tf32
__device__ float g_wpt[64 * 64];           // w_proj [j][o]

__global__ void prep_kernel(const float* __restrict__ wq,
                            const float* __restrict__ wk,
                            const float* __restrict__ wv,
                            const float* __restrict__ w_rel,
                            const float* __restrict__ w_deconv,
                            const float* __restrict__ w_proj)
{
    const int i0 = blockIdx.x * blockDim.x + threadIdx.x;
    const int stride = gridDim.x * blockDim.x;
    for (int i = i0; i < 4096; i += stride) {
        int o = i >> 6, c = i & 63;
        g_wpt[(c << 6) | o] = w_proj[i];
    }
    for (int j = i0; j < 12288; j += stride) {
        int r = j & 3, lane = (j >> 2) & 31, oct = (j >> 7) & 7, mt = j >> 10;
        int row = (lane >> 2) + ((r & 1) << 3);
        int k   = oct * 8 + (lane & 3) + ((r >> 1) << 2);
        const float* W = (mt < 4) ? wq : (mt < 8) ? wk : wv;
        g_wa1[j] = __uint_as_float(f2tf32(W[((mt & 3) * 16 + row) * 64 + k]));
    }
    for (int j = i0; j < 36864; j += stride) {
        int r = j & 3, lane = (j >> 2) & 31;
        int mo = j >> 7;
        int mt = mo / 72, oct = mo - mt * 72;
        int u = oct >> 3, jj = oct & 7;
        int ch = mt * 16 + (lane >> 2) + ((r & 1) << 3);
        int c  = jj * 8 + (lane & 3) + ((r >> 1) << 2);
        g_wa2[j] = __uint_as_float(f2tf32(w_rel[ch * 576 + c * 9 + u]));
    }
    for (int j = i0; j < 65536; j += stride) {
        int v    = j & 3;
        int lane = (j >> 2) & 31;
        int h    = (j >> 7) & 1;
        int n    = (j >> 8) & 3;
        int ch   = j >> 10;
        int e  = h * 8 + (lane & 3) + (v & 1) * 4;
        int bd = (lane >> 2) + (v >> 1) * 8;
        g_wd2[j] = __uint_as_float(f2tf32(w_deconv[ch * 1024 + (n * 16 + e) * 16 + bd]));
    }
}

// Dynamic smem layout (floats), total 18432 (73728 B):
//   PB(pi)=pi*4608 : per-patch scratch block (4608)
//     phase 0-2 : sp_pad sigma-interleaved [sig(c)][37] = PB+0..2367
//                 sp_lin [c][24]                        = PB+2368..3903
//     phase 2/3 : partials [8 warps][16][18]            = PB+0..2303
//     phase 4   : hbuf/abuf = PB+2304..3327, wbuf = PB+3328..4351
//   QB=9216  : q/k/v per patch: q=QB+pi*3456, k=+1152, v=+2304; each [4][16][18]
//   RB=16128 : relc_t per patch [16 ac][68] (+pi*1088)
//   CB=18304 : csum per patch [64]
#define SMEM_FLOATS 18432

__global__ __launch_bounds__(256, 2)
void selfattn2d_kernel(const float* __restrict__ x,
                       const float* __restrict__ w_sf1,
                       const float* __restrict__ b_sf1,
                       const float* __restrict__ w_sf2,
                       const float* __restrict__ b_sf2,
                       const float* __restrict__ b_proj,
                       float* __restrict__ out)
{
    extern __shared__ __align__(16) float S[];
    const int bid = blockIdx.x;
    const int b   = bid >> 9;
    const int t  = threadIdx.x;
    const int lane = t & 31;
    const int w    = t >> 5;

    int oys[2], oxs[2];
#pragma unroll
    for (int pi = 0; pi < 2; pi++) {
        int pb = bid * 2 + pi;
        oys[pi] = (pb >> 5) & 31;
        oxs[pi] = pb & 31;
    }

    // ---------------- Phase 0: load both patches ----------------
    {
        const float* xb = x + b * (64 * 64 * 64);
        for (int idx = t; idx < 4608; idx += 256) {
            int pi = (idx >= 2304) ? 1 : 0;
            int local = idx - pi * 2304;
            int c  = local / 36;
            int r  = local - c * 36;
            int ii = r / 6;
            int jj = r - ii * 6;
            int gy = oys[pi] * 2 + ii - 2;
            int gx = oxs[pi] * 2 + jj - 2;
            float val = 0.f;
            bool inpatch = (ii >= 1 && ii <= 4 && jj >= 1 && jj <= 4);
            if (inpatch && gy >= 0 && gy < 64 && gx >= 0 && gx < 64)
                val = xb[c * 4096 + gy * 64 + gx];
            val = __uint_as_float(f2tf32(val));
            S[pi * 4608 + ((c & 15) * 4 + (c >> 4)) * 37 + r] = val;
            if (inpatch)
                S[pi * 4608 + 2368 + c * 24 + (ii - 1) * 4 + (jj - 1)] = val;
        }
    }
    __syncthreads();

    // ---------------- Phase 1: q/k/v on tensor cores (A-frags shared) ----------------
    {
        const int base0 = (lane & 3) * 24 + (lane >> 2);
        const int row = lane >> 2, col = 2 * (lane & 3);
        const int nt = (w < 4) ? 1 : 2;
#pragma unroll
        for (int ti = 0; ti < 2; ti++) {
            if (ti >= nt) break;
            const int mt = (ti == 0) ? w : (w + 4);
            float acc[2][8];
#pragma unroll
            for (int pi = 0; pi < 2; pi++)
#pragma unroll
                for (int p = 0; p < 8; p++) acc[pi][p] = 0.f;
            const float4* wa = ((const float4*)g_wa1) + mt * 256 + lane;
#pragma unroll
            for (int oct = 0; oct < 8; oct++) {
                float4 A4 = wa[oct * 32];
#pragma unroll
                for (int pi = 0; pi < 2; pi++) {
                    const float* bp = S + pi * 4608 + 2368 + base0 + oct * 192;
                    float b0 = bp[0], b1 = bp[96];
                    float c0 = bp[8], c1 = bp[104];
                    mma_tf32(acc[pi][0], acc[pi][1], acc[pi][2], acc[pi][3],
                             fu(A4.x), fu(A4.y), fu(A4.z), fu(A4.w), fu(b0), fu(b1));
                    mma_tf32(acc[pi][4], acc[pi][5], acc[pi][6], acc[pi][7],
                             fu(A4.x), fu(A4.y), fu(A4.z), fu(A4.w), fu(c0), fu(c1));
                }
            }
            const float sc = (mt < 4) ? 0.25f : 1.0f;
#pragma unroll
            for (int pi = 0; pi < 2; pi++) {
                float* dst = S + 9216 + pi * 3456
                           + ((mt < 4) ? (mt * 288)
                              : (mt < 8) ? (1152 + (mt - 4) * 288)
                                         : (2304 + (mt - 8) * 288));
                *(float2*)(dst + row * 18 + col)           = make_float2(acc[pi][0] * sc, acc[pi][1] * sc);
                *(float2*)(dst + (row + 8) * 18 + col)     = make_float2(acc[pi][2] * sc, acc[pi][3] * sc);
                *(float2*)(dst + row * 18 + col + 8)       = make_float2(acc[pi][4] * sc, acc[pi][5] * sc);
                *(float2*)(dst + (row + 8) * 18 + col + 8) = make_float2(acc[pi][6] * sc, acc[pi][7] * sc);
            }
        }
    }

    // ---------------- Phase 2: rel_c conv on tensor cores (A-frags shared) ----------------
    {
        const int mt = w & 3, halfk = w >> 2;
        float acc[2][8];
#pragma unroll
        for (int pi = 0; pi < 2; pi++)
#pragma unroll
            for (int p = 0; p < 8; p++) acc[pi][p] = 0.f;
        const float4* wa = ((const float4*)g_wa2) + mt * 2304 + lane;
        const int q37 = (lane & 3) * 148;
        const int ac = lane >> 2;
        const int Pa = (ac >> 2) * 6 + (ac & 3);
#pragma unroll
        for (int u = 0; u < 9; u++) {
            bool mine = (halfk == 0) ? (u < 5) : (u >= 5);
            if (mine) {
                const int P = Pa + (u / 3) * 6 + (u % 3);
#pragma unroll
                for (int j = 0; j < 8; j++) {
                    float4 A4 = wa[(u * 8 + j) * 32];
                    const int boff = q37 + (j & 1) * 1184 + (j >> 1) * 37 + P;
#pragma unroll
                    for (int pi = 0; pi < 2; pi++) {
                        const float* sp = S + pi * 4608 + boff;
                        float b0 = sp[0],  b1 = sp[592];
                        float c0 = sp[12], c1 = sp[604];
                        mma_tf32(acc[pi][0], acc[pi][1], acc[pi][2], acc[pi][3],
                                 fu(A4.x), fu(A4.y), fu(A4.z), fu(A4.w), fu(b0), fu(b1));
                        mma_tf32(acc[pi][4], acc[pi][5], acc[pi][6], acc[pi][7],
                                 fu(A4.x), fu(A4.y), fu(A4.z), fu(A4.w), fu(c0), fu(c1));
                    }
                }
            }
        }
        __syncthreads();     // all patch reads complete before partial overwrite
        const int row = lane >> 2, col = 2 * (lane & 3);
#pragma unroll
        for (int pi = 0; pi < 2; pi++) {
            float* rp = S + pi * 4608 + w * 288;
            *(float2*)(rp + row * 18 + col)           = make_float2(acc[pi][0], acc[pi][1]);
            *(float2*)(rp + (row + 8) * 18 + col)     = make_float2(acc[pi][2], acc[pi][3]);
            *(float2*)(rp + row * 18 + col + 8)       = make_float2(acc[pi][4], acc[pi][5]);
            *(float2*)(rp + (row + 8) * 18 + col + 8) = make_float2(acc[pi][6], acc[pi][7]);
        }
    }
    __syncthreads();
    // reduce u-halves into relc_t[pi][ac][ch] (transposed, row stride 68)
    {
#pragma unroll
        for (int it = 0; it < 2; it++) {
            int task = t + it * 256;            // 512 tasks: pi(2) x ac(16) x chq(16)
            int pi = task >> 8;
            int rem = task & 255;
            int ac2 = rem >> 4;
            int chq = rem & 15;
            int mt2 = chq >> 2;
            const float* pa = S + pi * 4608 + mt2 * 288 + ((chq & 3) * 4) * 18 + ac2;
            const float* pb2 = pa + 4 * 288;
            float4 v4;
            v4.x = pa[0]  + pb2[0];
            v4.y = pa[18] + pb2[18];
            v4.z = pa[36] + pb2[36];
            v4.w = pa[54] + pb2[54];
            *(float4*)(S + 16128 + pi * 1088 + ac2 * 68 + chq * 4) = v4;
        }
    }
    __syncthreads();

    // ---------------- Phase 3: rel+q contraction (B-frags shared) ----------------
    {
        const int n    = w >> 1;
        const int ch0  = (w & 1) * 32;
        const int g    = lane >> 2;
        const int tg   = lane & 3;
        float qa[2][4], qb[2][4];
#pragma unroll
        for (int pi = 0; pi < 2; pi++) {
            const float* qbase = S + 9216 + pi * 3456 + n * 288;
#pragma unroll
            for (int j = 0; j < 4; j++) {
                qa[pi][j] = qbase[(tg + 4 * j) * 18 + g];
                qb[pi][j] = qbase[(tg + 4 * j) * 18 + g + 8];
            }
        }
        float acc[2][8];
#pragma unroll
        for (int pi = 0; pi < 2; pi++)
#pragma unroll
            for (int p = 0; p < 8; p++) acc[pi][p] = 0.f;
        const float4* wd4 = (const float4*)g_wd2;
#pragma unroll
        for (int cq = 0; cq < 8; cq++) {
            const int chb = ch0 + cq * 4;
            float4 r0q[2], r1q[2];
#pragma unroll
            for (int pi = 0; pi < 2; pi++) {
                const float* rc = S + 16128 + pi * 1088;
                r0q[pi] = *(const float4*)(rc + g * 68 + chb);
                r1q[pi] = *(const float4*)(rc + (g + 8) * 68 + chb);
            }
#pragma unroll
            for (int kk = 0; kk < 4; kk++) {
                const int ch = chb + kk;
#pragma unroll
                for (int h = 0; h < 2; h++) {
                    float4 B4 = wd4[((ch * 4 + n) * 2 + h) * 32 + lane];
#pragma unroll
                    for (int pi = 0; pi < 2; pi++) {
                        const float r0 = ((const float*)&r0q[pi])[kk];
                        const float r1 = ((const float*)&r1q[pi])[kk];
                        unsigned int a0 = f2tf32(r0 * qa[pi][2 * h + 0]);
                        unsigned int a1 = f2tf32(r1 * qb[pi][2 * h + 0]);
                        unsigned int a2 = f2tf32(r0 * qa[pi][2 * h + 1]);
                        unsigned int a3 = f2tf32(r1 * qb[pi][2 * h + 1]);
                        mma_tf32(acc[pi][0], acc[pi][1], acc[pi][2], acc[pi][3],
                                 a0, a1, a2, a3, fu(B4.x), fu(B4.y));
                        mma_tf32(acc[pi][4], acc[pi][5], acc[pi][6], acc[pi][7],
                                 a0, a1, a2, a3, fu(B4.z), fu(B4.w));
                    }
                }
            }
        }
#pragma unroll
        for (int pi = 0; pi < 2; pi++) {
            float* rp = S + pi * 4608 + w * 288;
            *(float2*)(rp + g * 18 + 2 * tg)           = make_float2(acc[pi][0], acc[pi][1]);
            *(float2*)(rp + (g + 8) * 18 + 2 * tg)     = make_float2(acc[pi][2], acc[pi][3]);
            *(float2*)(rp + g * 18 + 8 + 2 * tg)       = make_float2(acc[pi][4], acc[pi][5]);
            *(float2*)(rp + (g + 8) * 18 + 8 + 2 * tg) = make_float2(acc[pi][6], acc[pi][7]);
        }
    }
    __syncthreads();

    // ---------------- Phase 4: MLP + softmax + attention (256 threads) ----------------
    {
        const int pi = t >> 7, tl = t & 127;
        const int n = tl >> 5, p = (tl >> 1) & 15, hf = tl & 1;
        const int PB = pi * 4608;
        const int QB = 9216 + pi * 3456;
        const float* qc = S + QB + n * 288 + p;
        const float* kc = S + QB + 1152 + n * 288 + p;
        float h1v[8];
#pragma unroll
        for (int hh = 0; hh < 8; hh++) {
            int h = hf * 8 + hh;
            float s = b_sf1[h];
            const float* w1r = w_sf1 + h * 32;
#pragma unroll
            for (int d = 0; d < 16; d++) s += w1r[d] * qc[d * 18];
#pragma unroll
            for (int d = 0; d < 16; d++) s += w1r[16 + d] * kc[d * 18];
            h1v[hh] = tanhf(s);
        }
        float* hb = S + PB + 2304 + (n * 16 + p) * 16 + hf * 8;
        *(float4*)hb       = make_float4(h1v[0], h1v[1], h1v[2], h1v[3]);
        *(float4*)(hb + 4) = make_float4(h1v[4], h1v[5], h1v[6], h1v[7]);
    }
    __syncthreads();
    {
        const int pi = t >> 7, tl = t & 127;
        const int n = tl >> 5, p = (tl >> 1) & 15, hf = tl & 1;
        const int PB = pi * 4608;
        float hv[16];
        const float4* hb4 = (const float4*)(S + PB + 2304 + (n * 16 + p) * 16);
#pragma unroll
        for (int i4 = 0; i4 < 4; i4++) {
            float4 v4 = hb4[i4];
            hv[4 * i4] = v4.x; hv[4 * i4 + 1] = v4.y; hv[4 * i4 + 2] = v4.z; hv[4 * i4 + 3] = v4.w;
        }
        const float* rp0 = S + PB + (2 * n) * 288 + p * 18;
        const float* rp1 = rp0 + 288;
        float lg[8];
        float mx = -1e30f;
#pragma unroll
        for (int mm = 0; mm < 8; mm++) {
            int m = hf * 8 + mm;
            float s = b_sf2[m];
            const float* w2r = w_sf2 + m * 16;
#pragma unroll
            for (int h = 0; h < 16; h++) s += w2r[h] * hv[h];
            s += rp0[m] + rp1[m];
            lg[mm] = s;
            mx = fmaxf(mx, s);
        }
        mx = fmaxf(mx, __shfl_xor_sync(0xffffffffu, mx, 1));
        float den = 0.f;
#pragma unroll
        for (int mm = 0; mm < 8; mm++) { lg[mm] = __expf(lg[mm] - mx); den += lg[mm]; }
        den += __shfl_xor_sync(0xffffffffu, den, 1);
        const float inv = 1.0f / den;
        float* wb = S + PB + 3328 + (n * 16 + p) * 16 + hf * 8;
        *(float4*)wb       = make_float4(lg[0] * inv, lg[1] * inv, lg[2] * inv, lg[3] * inv);
        *(float4*)(wb + 4) = make_float4(lg[4] * inv, lg[5] * inv, lg[6] * inv, lg[7] * inv);
    }
    __syncthreads();
    {
        const int pi = t >> 7, tl = t & 127;
        const int n = tl >> 5, p = (tl >> 1) & 15, hf = tl & 1;
        const int PB = pi * 4608;
        float wv_[16];
        const float4* wb4 = (const float4*)(S + PB + 3328 + (n * 16 + p) * 16);
#pragma unroll
        for (int i4 = 0; i4 < 4; i4++) {
            float4 v4 = wb4[i4];
            wv_[4 * i4] = v4.x; wv_[4 * i4 + 1] = v4.y; wv_[4 * i4 + 2] = v4.z; wv_[4 * i4 + 3] = v4.w;
        }
        float av[8];
        const float* vbase = S + 9216 + pi * 3456 + 2304 + n * 288;
#pragma unroll
        for (int dd = 0; dd < 8; dd++) {
            int dv = hf * 8 + dd;
            const float2* vr = (const float2*)(vbase + dv * 18);
            float a = 0.f;
#pragma unroll
            for (int m2 = 0; m2 < 8; m2++) {
                float2 vv = vr[m2];
                a += wv_[2 * m2] * vv.x + wv_[2 * m2 + 1] * vv.y;
            }
            av[dd] = a;
        }
        float* ab = S + PB + 2304 + (n * 16 + p) * 16 + hf * 8;
        *(float4*)ab       = make_float4(av[0], av[1], av[2], av[3]);
        *(float4*)(ab + 4) = make_float4(av[4], av[5], av[6], av[7]);
    }
    __syncthreads();
    if (t < 128) {
        const int pi = t >> 6, tl = t & 63;
        const int plo = tl >> 4;
        const int dv  = tl & 15;
        const float* ab = S + pi * 4608 + 2304;
        float s = 0.f;
#pragma unroll
        for (int n2 = 0; n2 < 4; n2++)
#pragma unroll
            for (int ph = 0; ph < 4; ph++)
                s += ab[(n2 * 16 + ph * 4 + plo) * 16 + dv];
        S[18304 + pi * 64 + tl] = s;
    }
    __syncthreads();

    // ---------------- Phase 5: projection + sum ----------------
    if (t < 128) {
        const int pi = t >> 6, o = t & 63;
        const float* cs = S + 18304 + pi * 64;
        float acc = 16.0f * b_proj[o];
#pragma unroll 8
        for (int j = 0; j < 64; j++) acc += cs[j] * g_wpt[(j << 6) | o];
        out[b * 65536 + o * 1024 + oys[pi] * 32 + oxs[pi]] = acc;
    }
}

extern "C" void kernel_launch(void* const* d_in, const int* in_sizes, int n_in,
                              void* d_out, int out_size)
{
    (void)in_sizes; (void)n_in; (void)out_size;
    cudaFuncSetAttribute(selfattn2d_kernel,
                         cudaFuncAttributeMaxDynamicSharedMemorySize,
                         SMEM_FLOATS * sizeof(float));
    prep_kernel<<<64, 256>>>(
        (const float*)d_in[1],  // wq
        (const float*)d_in[2],  // wk
        (const float*)d_in[3],  // wv
        (const float*)d_in[4],  // w_rel
        (const float*)d_in[5],  // w_deconv
        (const float*)d_in[10]);// w_proj
    selfattn2d_kernel<<<2048, 256, SMEM_FLOATS * sizeof(float)>>>(
        (const float*)d_in[0],  // x
        (const float*)d_in[6],  // w_sf1
        (const float*)d_in[7],  // b_sf1
        (const float*)d_in[8],  // w_sf2
        (const float*)d_in[9],  // b_sf2
        (const float*)d_in[11], // b_proj
        (float*)d_out);
}